// round 3
// baseline (speedup 1.0000x reference)
#include <cuda_runtime.h>

// CIF: continuous integrate-and-fire.
// hidden [B,T,H] f32, alphas [B,T] f32, target_lengths [B] i32 -> out [B,L,H] f32.
#define BB 32
#define TT 2000
#define HH 512
#define LL 256
#define THRESH 0.95f
#define CHUNK 25              // 2000 = 80 * 25
#define NCHUNK (TT / CHUNK)

// Scratch (no device allocation allowed -> __device__ globals).
__device__ int2  g_tok[BB * LL];      // (fire time t, __float_as_int(cur)) per token
__device__ float g_scale[BB];         // per-batch alpha rescale factor
__device__ int   g_ntok[BB];          // number of emitted tokens (<= LL)
__device__ float g_aT[TT * BB];       // transposed scaled alphas: [t*32 + b] (L2-resident, 256KB)

// ---------------------------------------------------------------------------
// Kernel 1 (prep): per-batch alpha sum (double), scale, and transposed
// scaled-alpha buffer so the serial kernel's 32 lanes read coalesced lines.
// ---------------------------------------------------------------------------
__global__ void cif_prep_kernel(const float* __restrict__ alphas,
                                const int*   __restrict__ tlen)
{
    const int b = blockIdx.x;
    __shared__ float  sa[TT];
    __shared__ double red[256];
    __shared__ float  s_scale;

    const float* ab = alphas + (size_t)b * TT;

    double s = 0.0;
    for (int t = threadIdx.x; t < TT; t += 256) {
        float v = ab[t];
        sa[t] = v;
        s += (double)v;
    }
    red[threadIdx.x] = s;
    __syncthreads();
    #pragma unroll
    for (int o = 128; o > 0; o >>= 1) {
        if (threadIdx.x < o) red[threadIdx.x] += red[threadIdx.x + o];
        __syncthreads();
    }
    if (threadIdx.x == 0) {
        const float scale = (float)tlen[b] / (float)red[0];
        s_scale    = scale;
        g_scale[b] = scale;
    }
    __syncthreads();

    const float scale = s_scale;
    for (int t = threadIdx.x; t < TT; t += 256)
        g_aT[t * BB + b] = sa[t] * scale;
}

// ---------------------------------------------------------------------------
// Kernel 2 (serial scan): ONE warp; lane b replays batch b's exact sequential
// recurrence. Fully predicated body (no data-dependent branches), chunked
// double-buffered register prefetch from g_aT (coalesced across lanes).
// Loop-carried chain: FADD -> FSETP (pred-as-data) -> FSEL = 12 cyc/iter.
// ---------------------------------------------------------------------------
__global__ void cif_serial_kernel()
{
    const int b = threadIdx.x;                   // 0..31 = batch
    const float* __restrict__ aT = g_aT;
    int2* __restrict__ tok = g_tok + b * LL;

    float integ = 0.0f;
    int   k     = 0;

    float bufA[CHUNK], bufB[CHUNK];

    #pragma unroll
    for (int i = 0; i < CHUNK; i++)
        bufA[i] = aT[i * BB + b];

    #define PROCESS(BUF, TBASE)                                            \
        _Pragma("unroll")                                                  \
        for (int i = 0; i < CHUNK; i++) {                                  \
            const float a    = (BUF)[i];                                   \
            const float cur  = 1.0f - integ;      /* dist_completion */    \
            const float snew = integ + a;         /* FADD (chain) */       \
            const bool  fire = (snew >= THRESH);  /* FSETP (chain) */      \
            const float sm1  = snew - 1.0f;       /* exact (Sterbenz) */   \
            if (fire && k < LL)                   /* predicated STG.64 */  \
                tok[k] = make_int2((TBASE) + i, __float_as_int(cur));      \
            k += fire;                                                     \
            integ = fire ? sm1 : snew;            /* FSEL (chain) */       \
        }

    for (int c = 0; c < NCHUNK; c += 2) {
        #pragma unroll
        for (int i = 0; i < CHUNK; i++)
            bufB[i] = (c + 1 < NCHUNK) ? aT[((c + 1) * CHUNK + i) * BB + b] : 0.0f;
        PROCESS(bufA, c * CHUNK)
        #pragma unroll
        for (int i = 0; i < CHUNK; i++)
            bufA[i] = (c + 2 < NCHUNK) ? aT[((c + 2) * CHUNK + i) * BB + b] : 0.0f;
        PROCESS(bufB, (c + 1) * CHUNK)
    }
    #undef PROCESS

    g_ntok[b] = (k < LL) ? k : LL;
}

// ---------------------------------------------------------------------------
// Kernel 3 (gather): segmented weighted reduction of hidden -> out[b,k,:].
// Grid (L, B); 128 threads; thread owns one float4 (H=512). Boundary frames
// peeled; interior loop branch-free and unrolled x8 for MLP.
// wfirst (= remainds of previous fire) recomputed bit-exactly as
// alpha_scaled - cur_prev (same FADD the scan would have done).
// ---------------------------------------------------------------------------
__global__ void cif_gather_kernel(const float* __restrict__ hidden,
                                  const float* __restrict__ alphas,
                                  float*       __restrict__ out)
{
    const int k   = blockIdx.x;
    const int b   = blockIdx.y;
    const int tid = threadIdx.x;

    float4 acc = make_float4(0.f, 0.f, 0.f, 0.f);

    const int ntok = g_ntok[b];
    if (k < ntok) {
        const int2  tk    = g_tok[b * LL + k];
        const int   t1    = tk.x;
        const float wlast = __int_as_float(tk.y);
        const float scale = g_scale[b];
        const float* __restrict__ ap = alphas + (size_t)b * TT;
        const float4* __restrict__ hbase =
            reinterpret_cast<const float4*>(hidden + (size_t)b * TT * HH) + tid;

        int tstart;
        if (k == 0) {
            tstart = 0;
        } else {
            const int2  tp      = g_tok[b * LL + k - 1];
            const int   t0      = tp.x;
            const float curprev = __int_as_float(tp.y);
            const float wfirst  = ap[t0] * scale - curprev;   // == remainds (bit-exact)
            const float4 h0 = hbase[(size_t)t0 * (HH / 4)];
            acc.x = wfirst * h0.x; acc.y = wfirst * h0.y;
            acc.z = wfirst * h0.z; acc.w = wfirst * h0.w;
            tstart = t0 + 1;
        }

        #pragma unroll 8
        for (int t = tstart; t < t1; t++) {
            const float  w = ap[t] * scale;
            const float4 h = hbase[(size_t)t * (HH / 4)];
            acc.x += w * h.x; acc.y += w * h.y;
            acc.z += w * h.z; acc.w += w * h.w;
        }

        {
            const float4 h = hbase[(size_t)t1 * (HH / 4)];
            acc.x += wlast * h.x; acc.y += wlast * h.y;
            acc.z += wlast * h.z; acc.w += wlast * h.w;
        }
    }

    reinterpret_cast<float4*>(out + (size_t)(b * LL + k) * HH)[tid] = acc;
}

// ---------------------------------------------------------------------------
extern "C" void kernel_launch(void* const* d_in, const int* in_sizes, int n_in,
                              void* d_out, int out_size)
{
    const float* hidden = (const float*)d_in[0];   // [B,T,H]
    const float* alphas = (const float*)d_in[1];   // [B,T]
    const int*   tlen   = (const int*)  d_in[2];   // [B]
    float*       out    = (float*)d_out;           // [B,L,H]

    cif_prep_kernel<<<BB, 256>>>(alphas, tlen);
    cif_serial_kernel<<<1, 32>>>();

    dim3 grid(LL, BB);
    cif_gather_kernel<<<grid, 128>>>(hidden, alphas, out);
}